// round 9
// baseline (speedup 1.0000x reference)
#include <cuda_runtime.h>
#include <cuda_bf16.h>
#include <math.h>

#define N_NODES 50000
#define N_EDGES 600000
#define D 128
#define N_RELS 460

#define DEG_PAD 53248               // 13 blocks * 1024 threads * 4 items
#define SCAN_BLOCKS 13
#define SCORE_BLOCKS 198            // ceil((N_NODES+N_RELS)/256)
#define COUNT_BLOCKS 586            // ceil(N_EDGES/1024), 4 edges/thread
#define WSPLIT_BLOCKS 16            // 4096 fragment uint4s / 256
#define GEMM_BLOCKS 782             // ceil(N_NODES/64)
#define FLAG_BLOCKS 4               // ceil(GEMM_BLOCKS/256)

// ---------------- device scratch ----------------
__device__ __align__(16) int g_deg[DEG_PAD];
__device__ __align__(16) int g_off[DEG_PAD];     // exclusive prefix (padded; [N_NODES] valid)
__device__ int   g_scan_pub[SCAN_BLOCKS];        // inclusive+1; 0 = not ready
__device__ unsigned g_tflag[GEMM_BLOCKS];        // tile-done flags (reset by k_fill)
__device__ float g_s_src[N_NODES];
__device__ float g_s_dst[N_NODES];
__device__ float g_s_rel[N_RELS];
__device__ __align__(8) uint2 g_edge[N_EDGES];   // {exp(score) bits, src}, grouped by dst
// W^T in HMMA b-fragment order: [ntile(16)][ks(8)][lane(32)] = {bhi0,bhi1,blo0,blo1}
__device__ __align__(16) uint4 g_wfrag[16 * 8 * 32];

// ---------------- HMMA m16n8k16 bf16, fp32 acc ----------------
#define MMA16816(d, a, b0, b1)                                                  \
    asm volatile("mma.sync.aligned.m16n8k16.row.col.f32.bf16.bf16.f32 "         \
        "{%0,%1,%2,%3}, {%4,%5,%6,%7}, {%8,%9}, {%0,%1,%2,%3};"                 \
        : "+f"((d)[0]), "+f"((d)[1]), "+f"((d)[2]), "+f"((d)[3])                \
        : "r"((a)[0]), "r"((a)[1]), "r"((a)[2]), "r"((a)[3]),                   \
          "r"(b0), "r"(b1))

#define LDSM4(r, a)                                                             \
    asm volatile("ldmatrix.sync.aligned.m8n8.x4.shared.b16 {%0,%1,%2,%3}, [%4];" \
        : "=r"((r)[0]), "=r"((r)[1]), "=r"((r)[2]), "=r"((r)[3]) : "r"(a))

__device__ __forceinline__ unsigned smem_u32(const void* p) {
    unsigned a;
    asm("{ .reg .u64 t; cvta.to.shared.u64 t, %1; cvt.u32.u64 %0, t; }" : "=r"(a) : "l"(p));
    return a;
}
__device__ __forceinline__ unsigned pack_hi(float a, float b) {
    __nv_bfloat162 v = __floats2bfloat162_rn(a, b);
    return *(unsigned*)&v;
}

// ============================================================================
// K1: fused scores + degree count + W fragment-split + scan-flag reset.
// ============================================================================
__global__ void k_scores_count(const float* __restrict__ h,
                               const float* __restrict__ emb_rel,
                               const float* __restrict__ W,
                               const float* __restrict__ w2,
                               const int*   __restrict__ edst,
                               const float* __restrict__ loopW) {
    if (blockIdx.x < SCORE_BLOCKS) {
        __shared__ float su[3 * D];
        int t = threadIdx.x;
        {
            float s1 = 0.f, s2 = 0.f;
            #pragma unroll 4
            for (int o = 0; o < D; o++) {
                float c = w2[o];
                s1 += c * W[o * (3 * D) + t];
                if (t < 128) s2 += c * W[o * (3 * D) + t + 256];
            }
            su[t] = s1;
            if (t < 128) su[t + 256] = s2;
        }
        __syncthreads();
        int lane = t & 31;
        int wid  = t >> 5;
        float4 u0 = ((const float4*)su)[lane];
        float4 u1 = ((const float4*)su)[32 + lane];
        float4 u2 = ((const float4*)su)[64 + lane];
        int base = (blockIdx.x * 8 + wid) * 32;
        #pragma unroll 4
        for (int i = 0; i < 32; i++) {
            int gw = base + i;
            if (gw < N_NODES) {
                float4 hv = ((const float4*)h)[gw * 32 + lane];
                float ss = hv.x * u0.x + hv.y * u0.y + hv.z * u0.z + hv.w * u0.w;
                float sd = hv.x * u1.x + hv.y * u1.y + hv.z * u1.z + hv.w * u1.w;
                #pragma unroll
                for (int o = 16; o; o >>= 1) {
                    ss += __shfl_xor_sync(0xffffffffu, ss, o);
                    sd += __shfl_xor_sync(0xffffffffu, sd, o);
                }
                if (lane == 0) { g_s_src[gw] = ss; g_s_dst[gw] = sd; }
            } else if (gw < N_NODES + N_RELS) {
                int r = gw - N_NODES;
                float4 rv = ((const float4*)emb_rel)[r * 32 + lane];
                float sr = rv.x * u2.x + rv.y * u2.y + rv.z * u2.z + rv.w * u2.w;
                #pragma unroll
                for (int o = 16; o; o >>= 1) sr += __shfl_xor_sync(0xffffffffu, sr, o);
                if (lane == 0) g_s_rel[r] = sr;
            }
        }
    } else if (blockIdx.x < SCORE_BLOCKS + COUNT_BLOCKS) {
        int i4 = (blockIdx.x - SCORE_BLOCKS) * 256 + threadIdx.x;
        if (i4 * 4 < N_EDGES) {
            int4 d4 = ((const int4*)edst)[i4];
            atomicAdd(&g_deg[d4.x], 1);
            atomicAdd(&g_deg[d4.y], 1);
            atomicAdd(&g_deg[d4.z], 1);
            atomicAdd(&g_deg[d4.w], 1);
        }
    } else {
        // W -> HMMA b-fragment table (+ scan-flag reset); runs before k_scan
        int gid = (blockIdx.x - SCORE_BLOCKS - COUNT_BLOCKS) * 256 + threadIdx.x;
        if (gid < SCAN_BLOCKS) g_scan_pub[gid] = 0;
        int ntile = gid >> 8;            // 0..15
        int ks    = (gid >> 5) & 7;      // 0..7
        int lane  = gid & 31;
        int g = lane >> 2, t = lane & 3;
        int n  = ntile * 8 + g;
        int k0 = ks * 16 + 2 * t;
        float w00 = loopW[k0 * D + n];
        float w01 = loopW[(k0 + 1) * D + n];
        float w80 = loopW[(k0 + 8) * D + n];
        float w81 = loopW[(k0 + 9) * D + n];
        unsigned hi0 = pack_hi(w00, w01);
        unsigned hi1 = pack_hi(w80, w81);
        __nv_bfloat162 h0 = *(__nv_bfloat162*)&hi0;
        __nv_bfloat162 h1 = *(__nv_bfloat162*)&hi1;
        unsigned lo0 = pack_hi(w00 - __bfloat162float(__low2bfloat16(h0)),
                               w01 - __bfloat162float(__high2bfloat16(h0)));
        unsigned lo1 = pack_hi(w80 - __bfloat162float(__low2bfloat16(h1)),
                               w81 - __bfloat162float(__high2bfloat16(h1)));
        g_wfrag[gid] = make_uint4(hi0, hi1, lo0, lo1);
    }
}

// ============================================================================
// K2: decoupled-lookback exclusive scan, 13 blocks x 1024 thr x 4 items.
// ============================================================================
__global__ void __launch_bounds__(1024) k_scan() {
    __shared__ int sm[1024];
    __shared__ int s_prefix;
    int b = blockIdx.x, t = threadIdx.x;
    int4 v = ((const int4*)g_deg)[b * 1024 + t];
    int tot = v.x + v.y + v.z + v.w;
    sm[t] = tot;
    __syncthreads();
    #pragma unroll
    for (int off = 1; off < 1024; off <<= 1) {
        int val = (t >= off) ? sm[t - off] : 0;
        __syncthreads();
        sm[t] += val;
        __syncthreads();
    }
    if (t == 1023) {
        int inc = sm[1023];
        int p = 0;
        if (b > 0) {
            volatile int* pub = g_scan_pub;
            int x;
            do { x = pub[b - 1]; } while (x == 0);
            p = x - 1;
        }
        ((volatile int*)g_scan_pub)[b] = p + inc + 1;
        s_prefix = p;
    }
    __syncthreads();
    int pre = s_prefix + sm[t] - tot;
    int4 o;
    o.x = pre;
    o.y = pre + v.x;
    o.z = o.y + v.y;
    o.w = o.z + v.z;
    ((int4*)g_off)[b * 1024 + t] = o;
}

// ============================================================================
// K3: edge score -> exp, scatter packed {ex, src}; extra blocks reset tile flags
// ============================================================================
__global__ void k_fill(const int* __restrict__ esrc, const int* __restrict__ edst,
                       const int* __restrict__ etype) {
    if (blockIdx.x >= COUNT_BLOCKS) {
        int i = (blockIdx.x - COUNT_BLOCKS) * 256 + threadIdx.x;
        if (i < GEMM_BLOCKS) g_tflag[i] = 0;
        return;
    }
    int i4 = blockIdx.x * 256 + threadIdx.x;
    if (i4 * 4 >= N_EDGES) return;
    int4 s4 = ((const int4*)esrc)[i4];
    int4 d4 = ((const int4*)edst)[i4];
    int4 t4 = ((const int4*)etype)[i4];
    #pragma unroll
    for (int j = 0; j < 4; j++) {
        int s = (j == 0) ? s4.x : (j == 1) ? s4.y : (j == 2) ? s4.z : s4.w;
        int d = (j == 0) ? d4.x : (j == 1) ? d4.y : (j == 2) ? d4.z : d4.w;
        int r = (j == 0) ? t4.x : (j == 1) ? t4.y : (j == 2) ? t4.z : t4.w;
        float e = g_s_src[s] + g_s_dst[d] + g_s_rel[r];
        e = (e >= 0.f) ? e : 0.01f * e;
        int pos = g_off[d] + (atomicSub(&g_deg[d], 1) - 1);
        g_edge[pos] = make_uint2(__float_as_uint(__expf(e)), (unsigned)s);
    }
}

// ============================================================================
// K4: decoupled GEMM + aggregation in ONE launch.
//   blocks [0,782): HMMA GEMM tile (round-7 validated path), then flag.
//   blocks [782,1564): spin on tile flag, then per-dst softmax gather RMW.
// ============================================================================
#define A_STRIDE 272                        // 17*16: 16B-aligned rows
#define SM_A_HI  0
#define SM_A_LO  (64 * A_STRIDE)            // 17408
#define GEMM_SMEM (2 * 64 * A_STRIDE)       // 34816

__global__ void __launch_bounds__(256) k_gemm_agg(const float* __restrict__ h,
                                                  float* __restrict__ out) {
    extern __shared__ char smc[];
    int tid = threadIdx.x;
    int lane = tid & 31, wid = tid >> 5;

    if (blockIdx.x < GEMM_BLOCKS) {
        // ================= GEMM producer =================
        unsigned sb = smem_u32(smc);
        int row0 = blockIdx.x * 64;

        #pragma unroll
        for (int i = 0; i < 8; i++) {
            int idx = tid + i * 256;
            int r = idx >> 5, c4 = idx & 31;
            int row = row0 + r;
            float4 v = (row < N_NODES) ? ((const float4*)h)[row * 32 + c4]
                                       : make_float4(0.f, 0.f, 0.f, 0.f);
            __nv_bfloat162 h01 = __floats2bfloat162_rn(v.x, v.y);
            __nv_bfloat162 h23 = __floats2bfloat162_rn(v.z, v.w);
            float lx = v.x - __bfloat162float(__low2bfloat16(h01));
            float ly = v.y - __bfloat162float(__high2bfloat16(h01));
            float lz = v.z - __bfloat162float(__low2bfloat16(h23));
            float lw = v.w - __bfloat162float(__high2bfloat16(h23));
            __nv_bfloat162 l01 = __floats2bfloat162_rn(lx, ly);
            __nv_bfloat162 l23 = __floats2bfloat162_rn(lz, lw);
            unsigned off = r * A_STRIDE + c4 * 8;
            *(uint2*)(smc + SM_A_HI + off) = make_uint2(*(unsigned*)&h01, *(unsigned*)&h23);
            *(uint2*)(smc + SM_A_LO + off) = make_uint2(*(unsigned*)&l01, *(unsigned*)&l23);
        }
        __syncthreads();

        int g = lane >> 2, t = lane & 3;
        int wm = (wid & 1) * 32;
        int wn = (wid >> 1) * 32;

        unsigned aAddr = sb + SM_A_HI + (wm + (lane & 15)) * A_STRIDE + (lane >> 4) * 16;
        const uint4* __restrict__ wf = g_wfrag + (wn >> 3) * 256 + lane;

        float acc[2][4][4];
        #pragma unroll
        for (int a = 0; a < 2; a++)
            #pragma unroll
            for (int b2 = 0; b2 < 4; b2++)
                #pragma unroll
                for (int c = 0; c < 4; c++) acc[a][b2][c] = 0.f;

        #pragma unroll
        for (int ks = 0; ks < 8; ks++) {
            unsigned ahi[2][4], alo[2][4];
            #pragma unroll
            for (int mt = 0; mt < 2; mt++) {
                unsigned addr = aAddr + mt * (16 * A_STRIDE) + ks * 32;
                LDSM4(ahi[mt], addr);
                LDSM4(alo[mt], addr + (unsigned)SM_A_LO);
            }
            #pragma unroll
            for (int nt = 0; nt < 4; nt++) {
                uint4 f = wf[nt * 256 + ks * 32];
                #pragma unroll
                for (int mt = 0; mt < 2; mt++) {
                    MMA16816(acc[mt][nt], ahi[mt], f.x, f.y);
                    MMA16816(acc[mt][nt], ahi[mt], f.z, f.w);
                    MMA16816(acc[mt][nt], alo[mt], f.x, f.y);
                }
            }
        }

        #pragma unroll
        for (int mt = 0; mt < 2; mt++) {
            int r0 = blockIdx.x * 64 + wm + mt * 16 + g;
            #pragma unroll
            for (int nt = 0; nt < 4; nt++) {
                int col = wn + nt * 8 + 2 * t;
                if (r0 < N_NODES)
                    *(float2*)(out + r0 * D + col) = make_float2(acc[mt][nt][0], acc[mt][nt][1]);
                if (r0 + 8 < N_NODES)
                    *(float2*)(out + (r0 + 8) * D + col) = make_float2(acc[mt][nt][2], acc[mt][nt][3]);
            }
        }
        __threadfence();
        atomicAdd(&g_tflag[blockIdx.x], 1u);   // 256 arrivals = tile visible
    } else {
        // ================= aggregation consumer =================
        int tile = blockIdx.x - GEMM_BLOCKS;
        if (tid == 0) {
            unsigned v;
            do {
                asm volatile("ld.acquire.gpu.b32 %0, [%1];"
                             : "=r"(v) : "l"(&g_tflag[tile]) : "memory");
                if (v != 256u) __nanosleep(128);
            } while (v != 256u);
        }
        __syncthreads();

        #pragma unroll 1
        for (int i = 0; i < 8; i++) {
            int n = tile * 64 + wid * 8 + i;
            if (n >= N_NODES) break;
            int beg = g_off[n], end = g_off[n + 1];
            if (beg == end) continue;
            float4 a4 = {0.f, 0.f, 0.f, 0.f};
            float den = 0.f;
            int j = beg;
            for (; j + 4 <= end; j += 4) {
                uint2 e0 = g_edge[j],     e1 = g_edge[j + 1];
                uint2 e2 = g_edge[j + 2], e3 = g_edge[j + 3];
                float4 h0 = ((const float4*)h)[e0.y * 32 + lane];
                float4 h1 = ((const float4*)h)[e1.y * 32 + lane];
                float4 h2 = ((const float4*)h)[e2.y * 32 + lane];
                float4 h3 = ((const float4*)h)[e3.y * 32 + lane];
                float x0 = __uint_as_float(e0.x), x1 = __uint_as_float(e1.x);
                float x2 = __uint_as_float(e2.x), x3 = __uint_as_float(e3.x);
                den += (x0 + x1) + (x2 + x3);
                a4.x += x0 * h0.x + x1 * h1.x + x2 * h2.x + x3 * h3.x;
                a4.y += x0 * h0.y + x1 * h1.y + x2 * h2.y + x3 * h3.y;
                a4.z += x0 * h0.z + x1 * h1.z + x2 * h2.z + x3 * h3.z;
                a4.w += x0 * h0.w + x1 * h1.w + x2 * h2.w + x3 * h3.w;
            }
            for (; j < end; j++) {
                uint2 e0 = g_edge[j];
                float4 h0 = ((const float4*)h)[e0.y * 32 + lane];
                float x0 = __uint_as_float(e0.x);
                den += x0;
                a4.x += x0 * h0.x; a4.y += x0 * h0.y;
                a4.z += x0 * h0.z; a4.w += x0 * h0.w;
            }
            float inv = 1.f / den;
            float4* op = (float4*)out + n * 32 + lane;
            float4 o = *op;
            o.x += a4.x * inv; o.y += a4.y * inv;
            o.z += a4.z * inv; o.w += a4.w * inv;
            *op = o;
        }
    }
}

// ---------------- launch ----------------
extern "C" void kernel_launch(void* const* d_in, const int* in_sizes, int n_in,
                              void* d_out, int out_size) {
    const float* h          = (const float*)d_in[0];
    const float* emb_rel    = (const float*)d_in[1];
    const float* attn_fc_w  = (const float*)d_in[2];
    const float* attn_fc2_w = (const float*)d_in[3];
    const float* loop_w     = (const float*)d_in[4];
    const int*   esrc       = (const int*)d_in[5];
    const int*   edst       = (const int*)d_in[6];
    const int*   etype      = (const int*)d_in[7];
    float* out = (float*)d_out;

    cudaFuncSetAttribute(k_gemm_agg, cudaFuncAttributeMaxDynamicSharedMemorySize, GEMM_SMEM);

    k_scores_count<<<SCORE_BLOCKS + COUNT_BLOCKS + WSPLIT_BLOCKS, 256>>>(
        h, emb_rel, attn_fc_w, attn_fc2_w, edst, loop_w);
    k_scan<<<SCAN_BLOCKS, 1024>>>();
    k_fill<<<COUNT_BLOCKS + FLAG_BLOCKS, 256>>>(esrc, edst, etype);
    k_gemm_agg<<<2 * GEMM_BLOCKS, 256, GEMM_SMEM>>>(h, out);
}

// round 10
// speedup vs baseline: 1.1854x; 1.1854x over previous
#include <cuda_runtime.h>
#include <cuda_bf16.h>
#include <math.h>

#define N_NODES 50000
#define N_EDGES 600000
#define D 128
#define N_RELS 460

#define DEG_PAD 53248               // 13 blocks * 1024 threads * 4 items
#define SCAN_BLOCKS 13
#define SCORE_BLOCKS 198            // ceil((N_NODES+N_RELS)/256)
#define COUNT_BLOCKS 586            // ceil(N_EDGES/1024), 4 edges/thread
#define WSPLIT_BLOCKS 16            // 4096 fragment uint4s / 256
#define GEMM_BLOCKS 782             // ceil(N_NODES/64)

// ---------------- device scratch ----------------
__device__ __align__(16) int g_deg[DEG_PAD];
__device__ __align__(16) int g_off[DEG_PAD];     // exclusive prefix (padded; [N_NODES] valid)
__device__ int   g_scan_pub[SCAN_BLOCKS];        // inclusive+1; 0 = not ready
__device__ float g_s_src[N_NODES];
__device__ float g_s_dst[N_NODES];
__device__ float g_s_rel[N_RELS];
__device__ __align__(8) uint2 g_edge[N_EDGES];   // {exp(score) bits, src}, grouped by dst
// W^T in HMMA b-fragment order: [ntile(16)][ks(8)][lane(32)] = {bhi0,bhi1,blo0,blo1}
__device__ __align__(16) uint4 g_wfrag[16 * 8 * 32];

// ---------------- HMMA m16n8k16 bf16, fp32 acc ----------------
#define MMA16816(d, a, b0, b1)                                                  \
    asm volatile("mma.sync.aligned.m16n8k16.row.col.f32.bf16.bf16.f32 "         \
        "{%0,%1,%2,%3}, {%4,%5,%6,%7}, {%8,%9}, {%0,%1,%2,%3};"                 \
        : "+f"((d)[0]), "+f"((d)[1]), "+f"((d)[2]), "+f"((d)[3])                \
        : "r"((a)[0]), "r"((a)[1]), "r"((a)[2]), "r"((a)[3]),                   \
          "r"(b0), "r"(b1))

#define LDSM4(r, a)                                                             \
    asm volatile("ldmatrix.sync.aligned.m8n8.x4.shared.b16 {%0,%1,%2,%3}, [%4];" \
        : "=r"((r)[0]), "=r"((r)[1]), "=r"((r)[2]), "=r"((r)[3]) : "r"(a))

__device__ __forceinline__ unsigned smem_u32(const void* p) {
    unsigned a;
    asm("{ .reg .u64 t; cvta.to.shared.u64 t, %1; cvt.u32.u64 %0, t; }" : "=r"(a) : "l"(p));
    return a;
}
__device__ __forceinline__ unsigned pack_hi(float a, float b) {
    __nv_bfloat162 v = __floats2bfloat162_rn(a, b);
    return *(unsigned*)&v;
}

// ============================================================================
// K1: fused scores + degree count + W fragment-split + scan-flag reset.
// ============================================================================
__global__ void k_scores_count(const float* __restrict__ h,
                               const float* __restrict__ emb_rel,
                               const float* __restrict__ W,
                               const float* __restrict__ w2,
                               const int*   __restrict__ edst,
                               const float* __restrict__ loopW) {
    if (blockIdx.x < SCORE_BLOCKS) {
        __shared__ float su[3 * D];
        int t = threadIdx.x;
        {
            float s1 = 0.f, s2 = 0.f;
            #pragma unroll 16
            for (int o = 0; o < D; o++) {
                float c = w2[o];
                s1 += c * W[o * (3 * D) + t];
                if (t < 128) s2 += c * W[o * (3 * D) + t + 256];
            }
            su[t] = s1;
            if (t < 128) su[t + 256] = s2;
        }
        __syncthreads();
        int lane = t & 31;
        int wid  = t >> 5;
        float4 u0 = ((const float4*)su)[lane];
        float4 u1 = ((const float4*)su)[32 + lane];
        float4 u2 = ((const float4*)su)[64 + lane];
        int base = (blockIdx.x * 8 + wid) * 32;
        #pragma unroll 4
        for (int i = 0; i < 32; i++) {
            int gw = base + i;
            if (gw < N_NODES) {
                float4 hv = ((const float4*)h)[gw * 32 + lane];
                float ss = hv.x * u0.x + hv.y * u0.y + hv.z * u0.z + hv.w * u0.w;
                float sd = hv.x * u1.x + hv.y * u1.y + hv.z * u1.z + hv.w * u1.w;
                #pragma unroll
                for (int o = 16; o; o >>= 1) {
                    ss += __shfl_xor_sync(0xffffffffu, ss, o);
                    sd += __shfl_xor_sync(0xffffffffu, sd, o);
                }
                if (lane == 0) { g_s_src[gw] = ss; g_s_dst[gw] = sd; }
            } else if (gw < N_NODES + N_RELS) {
                int r = gw - N_NODES;
                float4 rv = ((const float4*)emb_rel)[r * 32 + lane];
                float sr = rv.x * u2.x + rv.y * u2.y + rv.z * u2.z + rv.w * u2.w;
                #pragma unroll
                for (int o = 16; o; o >>= 1) sr += __shfl_xor_sync(0xffffffffu, sr, o);
                if (lane == 0) g_s_rel[r] = sr;
            }
        }
    } else if (blockIdx.x < SCORE_BLOCKS + COUNT_BLOCKS) {
        int i4 = (blockIdx.x - SCORE_BLOCKS) * 256 + threadIdx.x;
        if (i4 * 4 < N_EDGES) {
            int4 d4 = ((const int4*)edst)[i4];
            atomicAdd(&g_deg[d4.x], 1);
            atomicAdd(&g_deg[d4.y], 1);
            atomicAdd(&g_deg[d4.z], 1);
            atomicAdd(&g_deg[d4.w], 1);
        }
    } else {
        // W -> HMMA b-fragment table (+ scan-flag reset); runs before k_scan
        int gid = (blockIdx.x - SCORE_BLOCKS - COUNT_BLOCKS) * 256 + threadIdx.x;
        if (gid < SCAN_BLOCKS) g_scan_pub[gid] = 0;
        int ntile = gid >> 8;            // 0..15
        int ks    = (gid >> 5) & 7;      // 0..7
        int lane  = gid & 31;
        int g = lane >> 2, t = lane & 3;
        int n  = ntile * 8 + g;
        int k0 = ks * 16 + 2 * t;
        float w00 = loopW[k0 * D + n];
        float w01 = loopW[(k0 + 1) * D + n];
        float w80 = loopW[(k0 + 8) * D + n];
        float w81 = loopW[(k0 + 9) * D + n];
        unsigned hi0 = pack_hi(w00, w01);
        unsigned hi1 = pack_hi(w80, w81);
        __nv_bfloat162 h0 = *(__nv_bfloat162*)&hi0;
        __nv_bfloat162 h1 = *(__nv_bfloat162*)&hi1;
        unsigned lo0 = pack_hi(w00 - __bfloat162float(__low2bfloat16(h0)),
                               w01 - __bfloat162float(__high2bfloat16(h0)));
        unsigned lo1 = pack_hi(w80 - __bfloat162float(__low2bfloat16(h1)),
                               w81 - __bfloat162float(__high2bfloat16(h1)));
        g_wfrag[gid] = make_uint4(hi0, hi1, lo0, lo1);
    }
}

// ============================================================================
// K2: decoupled-lookback exclusive scan, 13 blocks x 1024 thr x 4 items.
// ============================================================================
__global__ void __launch_bounds__(1024) k_scan() {
    __shared__ int sm[1024];
    __shared__ int s_prefix;
    int b = blockIdx.x, t = threadIdx.x;
    int4 v = ((const int4*)g_deg)[b * 1024 + t];
    int tot = v.x + v.y + v.z + v.w;
    sm[t] = tot;
    __syncthreads();
    #pragma unroll
    for (int off = 1; off < 1024; off <<= 1) {
        int val = (t >= off) ? sm[t - off] : 0;
        __syncthreads();
        sm[t] += val;
        __syncthreads();
    }
    if (t == 1023) {
        int inc = sm[1023];
        int p = 0;
        if (b > 0) {
            volatile int* pub = g_scan_pub;
            int x;
            do { x = pub[b - 1]; } while (x == 0);
            p = x - 1;
        }
        ((volatile int*)g_scan_pub)[b] = p + inc + 1;
        s_prefix = p;
    }
    __syncthreads();
    int pre = s_prefix + sm[t] - tot;
    int4 o;
    o.x = pre;
    o.y = pre + v.x;
    o.z = o.y + v.y;
    o.w = o.z + v.z;
    ((int4*)g_off)[b * 1024 + t] = o;
}

// ============================================================================
// K3: MERGED independent work: HMMA GEMM tile (blocks [0,782)) and
//     edge fill (blocks [782, 782+586)). No dependence between the halves.
// ============================================================================
#define A_STRIDE 272                        // 17*16: 16B-aligned rows
#define SM_A_HI  0
#define SM_A_LO  (64 * A_STRIDE)            // 17408
#define GEMM_SMEM (2 * 64 * A_STRIDE)       // 34816

__global__ void __launch_bounds__(256) k_gemm_fill(const float* __restrict__ h,
                                                   float* __restrict__ out,
                                                   const int* __restrict__ esrc,
                                                   const int* __restrict__ edst,
                                                   const int* __restrict__ etype) {
    extern __shared__ char smc[];
    int tid = threadIdx.x;

    if (blockIdx.x >= GEMM_BLOCKS) {
        // ================= edge fill =================
        int i4 = (blockIdx.x - GEMM_BLOCKS) * 256 + tid;
        if (i4 * 4 >= N_EDGES) return;
        int4 s4 = ((const int4*)esrc)[i4];
        int4 d4 = ((const int4*)edst)[i4];
        int4 t4 = ((const int4*)etype)[i4];
        #pragma unroll
        for (int j = 0; j < 4; j++) {
            int s = (j == 0) ? s4.x : (j == 1) ? s4.y : (j == 2) ? s4.z : s4.w;
            int d = (j == 0) ? d4.x : (j == 1) ? d4.y : (j == 2) ? d4.z : d4.w;
            int r = (j == 0) ? t4.x : (j == 1) ? t4.y : (j == 2) ? t4.z : t4.w;
            float e = g_s_src[s] + g_s_dst[d] + g_s_rel[r];
            e = (e >= 0.f) ? e : 0.01f * e;
            int pos = g_off[d] + (atomicSub(&g_deg[d], 1) - 1);
            g_edge[pos] = make_uint2(__float_as_uint(__expf(e)), (unsigned)s);
        }
        return;
    }

    // ================= GEMM (round-7 validated path) =================
    unsigned sb = smem_u32(smc);
    int lane = tid & 31, wid = tid >> 5;
    int row0 = blockIdx.x * 64;

    #pragma unroll
    for (int i = 0; i < 8; i++) {
        int idx = tid + i * 256;
        int r = idx >> 5, c4 = idx & 31;
        int row = row0 + r;
        float4 v = (row < N_NODES) ? ((const float4*)h)[row * 32 + c4]
                                   : make_float4(0.f, 0.f, 0.f, 0.f);
        __nv_bfloat162 h01 = __floats2bfloat162_rn(v.x, v.y);
        __nv_bfloat162 h23 = __floats2bfloat162_rn(v.z, v.w);
        float lx = v.x - __bfloat162float(__low2bfloat16(h01));
        float ly = v.y - __bfloat162float(__high2bfloat16(h01));
        float lz = v.z - __bfloat162float(__low2bfloat16(h23));
        float lw = v.w - __bfloat162float(__high2bfloat16(h23));
        __nv_bfloat162 l01 = __floats2bfloat162_rn(lx, ly);
        __nv_bfloat162 l23 = __floats2bfloat162_rn(lz, lw);
        unsigned off = r * A_STRIDE + c4 * 8;
        *(uint2*)(smc + SM_A_HI + off) = make_uint2(*(unsigned*)&h01, *(unsigned*)&h23);
        *(uint2*)(smc + SM_A_LO + off) = make_uint2(*(unsigned*)&l01, *(unsigned*)&l23);
    }
    __syncthreads();

    int g = lane >> 2, t = lane & 3;
    int wm = (wid & 1) * 32;
    int wn = (wid >> 1) * 32;

    unsigned aAddr = sb + SM_A_HI + (wm + (lane & 15)) * A_STRIDE + (lane >> 4) * 16;
    const uint4* __restrict__ wf = g_wfrag + (wn >> 3) * 256 + lane;

    float acc[2][4][4];
    #pragma unroll
    for (int a = 0; a < 2; a++)
        #pragma unroll
        for (int b2 = 0; b2 < 4; b2++)
            #pragma unroll
            for (int c = 0; c < 4; c++) acc[a][b2][c] = 0.f;

    #pragma unroll
    for (int ks = 0; ks < 8; ks++) {
        unsigned ahi[2][4], alo[2][4];
        #pragma unroll
        for (int mt = 0; mt < 2; mt++) {
            unsigned addr = aAddr + mt * (16 * A_STRIDE) + ks * 32;
            LDSM4(ahi[mt], addr);
            LDSM4(alo[mt], addr + (unsigned)SM_A_LO);
        }
        #pragma unroll
        for (int nt = 0; nt < 4; nt++) {
            uint4 f = wf[nt * 256 + ks * 32];
            #pragma unroll
            for (int mt = 0; mt < 2; mt++) {
                MMA16816(acc[mt][nt], ahi[mt], f.x, f.y);
                MMA16816(acc[mt][nt], ahi[mt], f.z, f.w);
                MMA16816(acc[mt][nt], alo[mt], f.x, f.y);
            }
        }
    }

    #pragma unroll
    for (int mt = 0; mt < 2; mt++) {
        int r0 = row0 + wm + mt * 16 + g;
        #pragma unroll
        for (int nt = 0; nt < 4; nt++) {
            int col = wn + nt * 8 + 2 * t;
            if (r0 < N_NODES)
                *(float2*)(out + r0 * D + col) = make_float2(acc[mt][nt][0], acc[mt][nt][1]);
            if (r0 + 8 < N_NODES)
                *(float2*)(out + (r0 + 8) * D + col) = make_float2(acc[mt][nt][2], acc[mt][nt][3]);
        }
    }
}

// ============================================================================
// K4: per-dst softmax-weighted gather-sum, v3.
//   Edge records loaded coalesced (1 LDG per 32 edges), broadcast via shfl;
//   gathers issued 4-deep (indices known upfront -> no load-load chain).
// ============================================================================
__global__ void k_aggregate(const float* __restrict__ h, float* __restrict__ out) {
    int lane = threadIdx.x & 31;
    int n = blockIdx.x * 8 + (threadIdx.x >> 5);
    if (n >= N_NODES) return;
    int beg = g_off[n], end = g_off[n + 1];
    if (beg == end) return;

    float4 acc = {0.f, 0.f, 0.f, 0.f};
    float den = 0.f;

    for (int c = beg; c < end; c += 32) {
        int m = end - c;
        if (m > 32) m = 32;
        uint2 er = make_uint2(0u, 0u);
        if (c + lane < end) er = g_edge[c + lane];
        int i = 0;
        for (; i + 4 <= m; i += 4) {
            unsigned f0 = __shfl_sync(0xffffffffu, er.x, i);
            unsigned s0 = __shfl_sync(0xffffffffu, er.y, i);
            unsigned f1 = __shfl_sync(0xffffffffu, er.x, i + 1);
            unsigned s1 = __shfl_sync(0xffffffffu, er.y, i + 1);
            unsigned f2 = __shfl_sync(0xffffffffu, er.x, i + 2);
            unsigned s2 = __shfl_sync(0xffffffffu, er.y, i + 2);
            unsigned f3 = __shfl_sync(0xffffffffu, er.x, i + 3);
            unsigned s3 = __shfl_sync(0xffffffffu, er.y, i + 3);
            float4 h0 = ((const float4*)h)[s0 * 32 + lane];
            float4 h1 = ((const float4*)h)[s1 * 32 + lane];
            float4 h2 = ((const float4*)h)[s2 * 32 + lane];
            float4 h3 = ((const float4*)h)[s3 * 32 + lane];
            float x0 = __uint_as_float(f0), x1 = __uint_as_float(f1);
            float x2 = __uint_as_float(f2), x3 = __uint_as_float(f3);
            den += (x0 + x1) + (x2 + x3);
            acc.x += x0 * h0.x + x1 * h1.x + x2 * h2.x + x3 * h3.x;
            acc.y += x0 * h0.y + x1 * h1.y + x2 * h2.y + x3 * h3.y;
            acc.z += x0 * h0.z + x1 * h1.z + x2 * h2.z + x3 * h3.z;
            acc.w += x0 * h0.w + x1 * h1.w + x2 * h2.w + x3 * h3.w;
        }
        for (; i < m; i++) {
            unsigned f0 = __shfl_sync(0xffffffffu, er.x, i);
            unsigned s0 = __shfl_sync(0xffffffffu, er.y, i);
            float4 h0 = ((const float4*)h)[s0 * 32 + lane];
            float x0 = __uint_as_float(f0);
            den += x0;
            acc.x += x0 * h0.x; acc.y += x0 * h0.y;
            acc.z += x0 * h0.z; acc.w += x0 * h0.w;
        }
    }

    float inv = 1.f / den;
    float4* op = (float4*)out + n * 32 + lane;
    float4 o = *op;
    o.x += acc.x * inv; o.y += acc.y * inv;
    o.z += acc.z * inv; o.w += acc.w * inv;
    *op = o;
}

// ---------------- launch ----------------
extern "C" void kernel_launch(void* const* d_in, const int* in_sizes, int n_in,
                              void* d_out, int out_size) {
    const float* h          = (const float*)d_in[0];
    const float* emb_rel    = (const float*)d_in[1];
    const float* attn_fc_w  = (const float*)d_in[2];
    const float* attn_fc2_w = (const float*)d_in[3];
    const float* loop_w     = (const float*)d_in[4];
    const int*   esrc       = (const int*)d_in[5];
    const int*   edst       = (const int*)d_in[6];
    const int*   etype      = (const int*)d_in[7];
    float* out = (float*)d_out;

    cudaFuncSetAttribute(k_gemm_fill, cudaFuncAttributeMaxDynamicSharedMemorySize, GEMM_SMEM);

    k_scores_count<<<SCORE_BLOCKS + COUNT_BLOCKS + WSPLIT_BLOCKS, 256>>>(
        h, emb_rel, attn_fc_w, attn_fc2_w, edst, loop_w);
    k_scan<<<SCAN_BLOCKS, 1024>>>();
    k_gemm_fill<<<GEMM_BLOCKS + COUNT_BLOCKS, 256, GEMM_SMEM>>>(h, out, esrc, edst, etype);
    k_aggregate<<<(N_NODES + 7) / 8, 256>>>(h, out);
}

// round 11
// speedup vs baseline: 1.2594x; 1.0625x over previous
#include <cuda_runtime.h>
#include <cuda_bf16.h>
#include <math.h>

#define N_NODES 50000
#define N_EDGES 600000
#define D 128
#define N_RELS 460

#define DEG_PAD 53248               // 13 blocks * 1024 threads * 4 items
#define SCAN_BLOCKS 13
#define SCORE_BLOCKS 198            // ceil((N_NODES+N_RELS)/256)
#define COUNT_BLOCKS 586            // ceil(N_EDGES/1024), 4 edges/thread
#define WSPLIT_BLOCKS 16            // 4096 fragment uint4s / 256
#define GEMM_BLOCKS 782             // ceil(N_NODES/64)

// ---------------- device scratch ----------------
__device__ __align__(16) int g_deg[DEG_PAD];
__device__ __align__(16) int g_off[DEG_PAD];     // exclusive prefix (padded; [N_NODES] valid)
__device__ int   g_scan_pub[SCAN_BLOCKS];        // inclusive+1; 0 = not ready
__device__ float g_s_src[N_NODES];
__device__ float g_s_dst[N_NODES];
__device__ float g_s_rel[N_RELS];
__device__ __align__(8) uint2 g_edge[N_EDGES];   // {exp(score) bits, src}, grouped by dst
// W^T in HMMA b-fragment order: [ntile(16)][ks(8)][lane(32)] = {bhi0,bhi1,blo0,blo1}
__device__ __align__(16) uint4 g_wfrag[16 * 8 * 32];

// ---------------- HMMA m16n8k16 bf16, fp32 acc ----------------
#define MMA16816(d, a, b0, b1)                                                  \
    asm volatile("mma.sync.aligned.m16n8k16.row.col.f32.bf16.bf16.f32 "         \
        "{%0,%1,%2,%3}, {%4,%5,%6,%7}, {%8,%9}, {%0,%1,%2,%3};"                 \
        : "+f"((d)[0]), "+f"((d)[1]), "+f"((d)[2]), "+f"((d)[3])                \
        : "r"((a)[0]), "r"((a)[1]), "r"((a)[2]), "r"((a)[3]),                   \
          "r"(b0), "r"(b1))

#define LDSM4(r, a)                                                             \
    asm volatile("ldmatrix.sync.aligned.m8n8.x4.shared.b16 {%0,%1,%2,%3}, [%4];" \
        : "=r"((r)[0]), "=r"((r)[1]), "=r"((r)[2]), "=r"((r)[3]) : "r"(a))

__device__ __forceinline__ unsigned smem_u32(const void* p) {
    unsigned a;
    asm("{ .reg .u64 t; cvta.to.shared.u64 t, %1; cvt.u32.u64 %0, t; }" : "=r"(a) : "l"(p));
    return a;
}
__device__ __forceinline__ unsigned pack_hi(float a, float b) {
    __nv_bfloat162 v = __floats2bfloat162_rn(a, b);
    return *(unsigned*)&v;
}

// ============================================================================
// K1: fused scores + degree count + W fragment-split + scan-flag reset.
// ============================================================================
__global__ void k_scores_count(const float* __restrict__ h,
                               const float* __restrict__ emb_rel,
                               const float* __restrict__ W,
                               const float* __restrict__ w2,
                               const int*   __restrict__ edst,
                               const float* __restrict__ loopW) {
    if (blockIdx.x < SCORE_BLOCKS) {
        __shared__ float su[3 * D];
        int t = threadIdx.x;
        {
            float s1 = 0.f, s2 = 0.f;
            #pragma unroll 16
            for (int o = 0; o < D; o++) {
                float c = w2[o];
                s1 += c * W[o * (3 * D) + t];
                if (t < 128) s2 += c * W[o * (3 * D) + t + 256];
            }
            su[t] = s1;
            if (t < 128) su[t + 256] = s2;
        }
        __syncthreads();
        int lane = t & 31;
        int wid  = t >> 5;
        float4 u0 = ((const float4*)su)[lane];
        float4 u1 = ((const float4*)su)[32 + lane];
        float4 u2 = ((const float4*)su)[64 + lane];
        int base = (blockIdx.x * 8 + wid) * 32;
        #pragma unroll 4
        for (int i = 0; i < 32; i++) {
            int gw = base + i;
            if (gw < N_NODES) {
                float4 hv = ((const float4*)h)[gw * 32 + lane];
                float ss = hv.x * u0.x + hv.y * u0.y + hv.z * u0.z + hv.w * u0.w;
                float sd = hv.x * u1.x + hv.y * u1.y + hv.z * u1.z + hv.w * u1.w;
                #pragma unroll
                for (int o = 16; o; o >>= 1) {
                    ss += __shfl_xor_sync(0xffffffffu, ss, o);
                    sd += __shfl_xor_sync(0xffffffffu, sd, o);
                }
                if (lane == 0) { g_s_src[gw] = ss; g_s_dst[gw] = sd; }
            } else if (gw < N_NODES + N_RELS) {
                int r = gw - N_NODES;
                float4 rv = ((const float4*)emb_rel)[r * 32 + lane];
                float sr = rv.x * u2.x + rv.y * u2.y + rv.z * u2.z + rv.w * u2.w;
                #pragma unroll
                for (int o = 16; o; o >>= 1) sr += __shfl_xor_sync(0xffffffffu, sr, o);
                if (lane == 0) g_s_rel[r] = sr;
            }
        }
    } else if (blockIdx.x < SCORE_BLOCKS + COUNT_BLOCKS) {
        int i4 = (blockIdx.x - SCORE_BLOCKS) * 256 + threadIdx.x;
        if (i4 * 4 < N_EDGES) {
            int4 d4 = ((const int4*)edst)[i4];
            atomicAdd(&g_deg[d4.x], 1);
            atomicAdd(&g_deg[d4.y], 1);
            atomicAdd(&g_deg[d4.z], 1);
            atomicAdd(&g_deg[d4.w], 1);
        }
    } else {
        // W -> HMMA b-fragment table (+ scan-flag reset); runs before k_scan
        int gid = (blockIdx.x - SCORE_BLOCKS - COUNT_BLOCKS) * 256 + threadIdx.x;
        if (gid < SCAN_BLOCKS) g_scan_pub[gid] = 0;
        int ntile = gid >> 8;            // 0..15
        int ks    = (gid >> 5) & 7;      // 0..7
        int lane  = gid & 31;
        int g = lane >> 2, t = lane & 3;
        int n  = ntile * 8 + g;
        int k0 = ks * 16 + 2 * t;
        float w00 = loopW[k0 * D + n];
        float w01 = loopW[(k0 + 1) * D + n];
        float w80 = loopW[(k0 + 8) * D + n];
        float w81 = loopW[(k0 + 9) * D + n];
        unsigned hi0 = pack_hi(w00, w01);
        unsigned hi1 = pack_hi(w80, w81);
        __nv_bfloat162 h0 = *(__nv_bfloat162*)&hi0;
        __nv_bfloat162 h1 = *(__nv_bfloat162*)&hi1;
        unsigned lo0 = pack_hi(w00 - __bfloat162float(__low2bfloat16(h0)),
                               w01 - __bfloat162float(__high2bfloat16(h0)));
        unsigned lo1 = pack_hi(w80 - __bfloat162float(__low2bfloat16(h1)),
                               w81 - __bfloat162float(__high2bfloat16(h1)));
        g_wfrag[gid] = make_uint4(hi0, hi1, lo0, lo1);
    }
}

// ============================================================================
// K2: decoupled-lookback exclusive scan, 13 blocks x 1024 thr x 4 items.
// ============================================================================
__global__ void __launch_bounds__(1024) k_scan() {
    __shared__ int sm[1024];
    __shared__ int s_prefix;
    int b = blockIdx.x, t = threadIdx.x;
    int4 v = ((const int4*)g_deg)[b * 1024 + t];
    int tot = v.x + v.y + v.z + v.w;
    sm[t] = tot;
    __syncthreads();
    #pragma unroll
    for (int off = 1; off < 1024; off <<= 1) {
        int val = (t >= off) ? sm[t - off] : 0;
        __syncthreads();
        sm[t] += val;
        __syncthreads();
    }
    if (t == 1023) {
        int inc = sm[1023];
        int p = 0;
        if (b > 0) {
            volatile int* pub = g_scan_pub;
            int x;
            do { x = pub[b - 1]; } while (x == 0);
            p = x - 1;
        }
        ((volatile int*)g_scan_pub)[b] = p + inc + 1;
        s_prefix = p;
    }
    __syncthreads();
    int pre = s_prefix + sm[t] - tot;
    int4 o;
    o.x = pre;
    o.y = pre + v.x;
    o.z = o.y + v.y;
    o.w = o.z + v.z;
    ((int4*)g_off)[b * 1024 + t] = o;
}

// ============================================================================
// K3: MERGED independent work: HMMA GEMM tile (blocks [0,782)) and
//     edge fill (blocks [782, 782+586)). No dependence between the halves.
// ============================================================================
#define A_STRIDE 272                        // 17*16: 16B-aligned rows
#define SM_A_HI  0
#define SM_A_LO  (64 * A_STRIDE)            // 17408
#define GEMM_SMEM (2 * 64 * A_STRIDE)       // 34816

__global__ void __launch_bounds__(256) k_gemm_fill(const float* __restrict__ h,
                                                   float* __restrict__ out,
                                                   const int* __restrict__ esrc,
                                                   const int* __restrict__ edst,
                                                   const int* __restrict__ etype) {
    extern __shared__ char smc[];
    int tid = threadIdx.x;

    if (blockIdx.x >= GEMM_BLOCKS) {
        // ================= edge fill =================
        int i4 = (blockIdx.x - GEMM_BLOCKS) * 256 + tid;
        if (i4 * 4 >= N_EDGES) return;
        int4 s4 = ((const int4*)esrc)[i4];
        int4 d4 = ((const int4*)edst)[i4];
        int4 t4 = ((const int4*)etype)[i4];
        #pragma unroll
        for (int j = 0; j < 4; j++) {
            int s = (j == 0) ? s4.x : (j == 1) ? s4.y : (j == 2) ? s4.z : s4.w;
            int d = (j == 0) ? d4.x : (j == 1) ? d4.y : (j == 2) ? d4.z : d4.w;
            int r = (j == 0) ? t4.x : (j == 1) ? t4.y : (j == 2) ? t4.z : t4.w;
            float e = g_s_src[s] + g_s_dst[d] + g_s_rel[r];
            e = (e >= 0.f) ? e : 0.01f * e;
            int pos = g_off[d] + (atomicSub(&g_deg[d], 1) - 1);
            g_edge[pos] = make_uint2(__float_as_uint(__expf(e)), (unsigned)s);
        }
        return;
    }

    // ================= GEMM (round-7 validated path) =================
    unsigned sb = smem_u32(smc);
    int lane = tid & 31, wid = tid >> 5;
    int row0 = blockIdx.x * 64;

    #pragma unroll
    for (int i = 0; i < 8; i++) {
        int idx = tid + i * 256;
        int r = idx >> 5, c4 = idx & 31;
        int row = row0 + r;
        float4 v = (row < N_NODES) ? ((const float4*)h)[row * 32 + c4]
                                   : make_float4(0.f, 0.f, 0.f, 0.f);
        __nv_bfloat162 h01 = __floats2bfloat162_rn(v.x, v.y);
        __nv_bfloat162 h23 = __floats2bfloat162_rn(v.z, v.w);
        float lx = v.x - __bfloat162float(__low2bfloat16(h01));
        float ly = v.y - __bfloat162float(__high2bfloat16(h01));
        float lz = v.z - __bfloat162float(__low2bfloat16(h23));
        float lw = v.w - __bfloat162float(__high2bfloat16(h23));
        __nv_bfloat162 l01 = __floats2bfloat162_rn(lx, ly);
        __nv_bfloat162 l23 = __floats2bfloat162_rn(lz, lw);
        unsigned off = r * A_STRIDE + c4 * 8;
        *(uint2*)(smc + SM_A_HI + off) = make_uint2(*(unsigned*)&h01, *(unsigned*)&h23);
        *(uint2*)(smc + SM_A_LO + off) = make_uint2(*(unsigned*)&l01, *(unsigned*)&l23);
    }
    __syncthreads();

    int g = lane >> 2, t = lane & 3;
    int wm = (wid & 1) * 32;
    int wn = (wid >> 1) * 32;

    unsigned aAddr = sb + SM_A_HI + (wm + (lane & 15)) * A_STRIDE + (lane >> 4) * 16;
    const uint4* __restrict__ wf = g_wfrag + (wn >> 3) * 256 + lane;

    float acc[2][4][4];
    #pragma unroll
    for (int a = 0; a < 2; a++)
        #pragma unroll
        for (int b2 = 0; b2 < 4; b2++)
            #pragma unroll
            for (int c = 0; c < 4; c++) acc[a][b2][c] = 0.f;

    #pragma unroll
    for (int ks = 0; ks < 8; ks++) {
        unsigned ahi[2][4], alo[2][4];
        #pragma unroll
        for (int mt = 0; mt < 2; mt++) {
            unsigned addr = aAddr + mt * (16 * A_STRIDE) + ks * 32;
            LDSM4(ahi[mt], addr);
            LDSM4(alo[mt], addr + (unsigned)SM_A_LO);
        }
        #pragma unroll
        for (int nt = 0; nt < 4; nt++) {
            uint4 f = wf[nt * 256 + ks * 32];
            #pragma unroll
            for (int mt = 0; mt < 2; mt++) {
                MMA16816(acc[mt][nt], ahi[mt], f.x, f.y);
                MMA16816(acc[mt][nt], ahi[mt], f.z, f.w);
                MMA16816(acc[mt][nt], alo[mt], f.x, f.y);
            }
        }
    }

    #pragma unroll
    for (int mt = 0; mt < 2; mt++) {
        int r0 = row0 + wm + mt * 16 + g;
        #pragma unroll
        for (int nt = 0; nt < 4; nt++) {
            int col = wn + nt * 8 + 2 * t;
            if (r0 < N_NODES)
                *(float2*)(out + r0 * D + col) = make_float2(acc[mt][nt][0], acc[mt][nt][1]);
            if (r0 + 8 < N_NODES)
                *(float2*)(out + (r0 + 8) * D + col) = make_float2(acc[mt][nt][2], acc[mt][nt][3]);
        }
    }
}

// ============================================================================
// K4: per-dst softmax-weighted gather-sum.
//   Direct lane-uniform edge-record loads (L1-resident, sequential) +
//   4-deep independent gathers (addresses ready early -> MLP ~4).
// ============================================================================
__global__ void k_aggregate(const float* __restrict__ h, float* __restrict__ out) {
    int lane = threadIdx.x & 31;
    int n = blockIdx.x * 8 + (threadIdx.x >> 5);
    if (n >= N_NODES) return;
    int beg = g_off[n], end = g_off[n + 1];
    if (beg == end) return;

    float4 acc = {0.f, 0.f, 0.f, 0.f};
    float den = 0.f;
    int j = beg;
    for (; j + 4 <= end; j += 4) {
        uint2 e0 = g_edge[j],     e1 = g_edge[j + 1];
        uint2 e2 = g_edge[j + 2], e3 = g_edge[j + 3];
        float4 h0 = ((const float4*)h)[e0.y * 32 + lane];
        float4 h1 = ((const float4*)h)[e1.y * 32 + lane];
        float4 h2 = ((const float4*)h)[e2.y * 32 + lane];
        float4 h3 = ((const float4*)h)[e3.y * 32 + lane];
        float x0 = __uint_as_float(e0.x), x1 = __uint_as_float(e1.x);
        float x2 = __uint_as_float(e2.x), x3 = __uint_as_float(e3.x);
        den += (x0 + x1) + (x2 + x3);
        acc.x += x0 * h0.x + x1 * h1.x + x2 * h2.x + x3 * h3.x;
        acc.y += x0 * h0.y + x1 * h1.y + x2 * h2.y + x3 * h3.y;
        acc.z += x0 * h0.z + x1 * h1.z + x2 * h2.z + x3 * h3.z;
        acc.w += x0 * h0.w + x1 * h1.w + x2 * h2.w + x3 * h3.w;
    }
    for (; j < end; j++) {
        uint2 e0 = g_edge[j];
        float4 h0 = ((const float4*)h)[e0.y * 32 + lane];
        float x0 = __uint_as_float(e0.x);
        den += x0;
        acc.x += x0 * h0.x; acc.y += x0 * h0.y;
        acc.z += x0 * h0.z; acc.w += x0 * h0.w;
    }
    float inv = 1.f / den;
    float4* op = (float4*)out + n * 32 + lane;
    float4 o = *op;
    o.x += acc.x * inv; o.y += acc.y * inv;
    o.z += acc.z * inv; o.w += acc.w * inv;
    *op = o;
}

// ---------------- launch ----------------
extern "C" void kernel_launch(void* const* d_in, const int* in_sizes, int n_in,
                              void* d_out, int out_size) {
    const float* h          = (const float*)d_in[0];
    const float* emb_rel    = (const float*)d_in[1];
    const float* attn_fc_w  = (const float*)d_in[2];
    const float* attn_fc2_w = (const float*)d_in[3];
    const float* loop_w     = (const float*)d_in[4];
    const int*   esrc       = (const int*)d_in[5];
    const int*   edst       = (const int*)d_in[6];
    const int*   etype      = (const int*)d_in[7];
    float* out = (float*)d_out;

    cudaFuncSetAttribute(k_gemm_fill, cudaFuncAttributeMaxDynamicSharedMemorySize, GEMM_SMEM);

    k_scores_count<<<SCORE_BLOCKS + COUNT_BLOCKS + WSPLIT_BLOCKS, 256>>>(
        h, emb_rel, attn_fc_w, attn_fc2_w, edst, loop_w);
    k_scan<<<SCAN_BLOCKS, 1024>>>();
    k_gemm_fill<<<GEMM_BLOCKS + COUNT_BLOCKS, 256, GEMM_SMEM>>>(h, out, esrc, edst, etype);
    k_aggregate<<<(N_NODES + 7) / 8, 256>>>(h, out);
}

// round 12
// speedup vs baseline: 1.3567x; 1.0772x over previous
#include <cuda_runtime.h>
#include <cuda_bf16.h>
#include <math.h>

#define N_NODES 50000
#define N_EDGES 600000
#define D 128
#define N_RELS 460

#define DEG_PAD 53248               // 13 blocks * 1024 threads * 4 items
#define SCAN_BLOCKS 13
#define COUNT_BLOCKS 586            // ceil(N_EDGES/1024), 4 edges/thread
#define WSPLIT_BLOCKS 16            // 4096 fragment uint4s / 256
#define U_BLOCKS 2                  // 384 u-outputs / 256
#define SCORE_BLOCKS 50             // ceil((N_NODES+N_RELS)/1024)
#define GEMM_BLOCKS 782             // ceil(N_NODES/64)

// ---------------- device scratch ----------------
__device__ __align__(16) int g_deg[DEG_PAD];
__device__ __align__(16) int g_off[DEG_PAD];     // exclusive prefix (padded; [N_NODES] valid)
__device__ int   g_scan_pub[SCAN_BLOCKS];        // inclusive+1; 0 = not ready
__device__ __align__(16) float g_u[3 * D];       // collapsed attention vector
__device__ float g_s_src[N_NODES];
__device__ float g_s_dst[N_NODES];
__device__ float g_s_rel[N_RELS];
__device__ __align__(8) uint2 g_edge[N_EDGES];   // {exp(score) bits, src}, grouped by dst
// W^T in HMMA b-fragment order: [ntile(16)][ks(8)][lane(32)] = {bhi0,bhi1,blo0,blo1}
__device__ __align__(16) uint4 g_wfrag[16 * 8 * 32];

// ---------------- HMMA m16n8k16 bf16, fp32 acc ----------------
#define MMA16816(d, a, b0, b1)                                                  \
    asm volatile("mma.sync.aligned.m16n8k16.row.col.f32.bf16.bf16.f32 "         \
        "{%0,%1,%2,%3}, {%4,%5,%6,%7}, {%8,%9}, {%0,%1,%2,%3};"                 \
        : "+f"((d)[0]), "+f"((d)[1]), "+f"((d)[2]), "+f"((d)[3])                \
        : "r"((a)[0]), "r"((a)[1]), "r"((a)[2]), "r"((a)[3]),                   \
          "r"(b0), "r"(b1))

#define LDSM4(r, a)                                                             \
    asm volatile("ldmatrix.sync.aligned.m8n8.x4.shared.b16 {%0,%1,%2,%3}, [%4];" \
        : "=r"((r)[0]), "=r"((r)[1]), "=r"((r)[2]), "=r"((r)[3]) : "r"(a))

__device__ __forceinline__ unsigned smem_u32(const void* p) {
    unsigned a;
    asm("{ .reg .u64 t; cvta.to.shared.u64 t, %1; cvt.u32.u64 %0, t; }" : "=r"(a) : "l"(p));
    return a;
}
__device__ __forceinline__ unsigned pack_hi(float a, float b) {
    __nv_bfloat162 v = __floats2bfloat162_rn(a, b);
    return *(unsigned*)&v;
}

// ============================================================================
// K1: degree count + W fragment-split + u-compute + scan-flag reset.
// ============================================================================
__global__ void k_prep(const float* __restrict__ W,
                       const float* __restrict__ w2,
                       const int*   __restrict__ edst,
                       const float* __restrict__ loopW) {
    if (blockIdx.x < COUNT_BLOCKS) {
        int i4 = blockIdx.x * 256 + threadIdx.x;
        if (i4 * 4 < N_EDGES) {
            int4 d4 = ((const int4*)edst)[i4];
            atomicAdd(&g_deg[d4.x], 1);
            atomicAdd(&g_deg[d4.y], 1);
            atomicAdd(&g_deg[d4.z], 1);
            atomicAdd(&g_deg[d4.w], 1);
        }
    } else if (blockIdx.x < COUNT_BLOCKS + WSPLIT_BLOCKS) {
        // W -> HMMA b-fragment table (+ scan-flag reset)
        int gid = (blockIdx.x - COUNT_BLOCKS) * 256 + threadIdx.x;
        if (gid < SCAN_BLOCKS) g_scan_pub[gid] = 0;
        int ntile = gid >> 8;            // 0..15
        int ks    = (gid >> 5) & 7;      // 0..7
        int lane  = gid & 31;
        int g = lane >> 2, t = lane & 3;
        int n  = ntile * 8 + g;
        int k0 = ks * 16 + 2 * t;
        float w00 = loopW[k0 * D + n];
        float w01 = loopW[(k0 + 1) * D + n];
        float w80 = loopW[(k0 + 8) * D + n];
        float w81 = loopW[(k0 + 9) * D + n];
        unsigned hi0 = pack_hi(w00, w01);
        unsigned hi1 = pack_hi(w80, w81);
        __nv_bfloat162 h0 = *(__nv_bfloat162*)&hi0;
        __nv_bfloat162 h1 = *(__nv_bfloat162*)&hi1;
        unsigned lo0 = pack_hi(w00 - __bfloat162float(__low2bfloat16(h0)),
                               w01 - __bfloat162float(__high2bfloat16(h0)));
        unsigned lo1 = pack_hi(w80 - __bfloat162float(__low2bfloat16(h1)),
                               w81 - __bfloat162float(__high2bfloat16(h1)));
        g_wfrag[gid] = make_uint4(hi0, hi1, lo0, lo1);
    } else {
        // u = attn_fc_w.T @ attn_fc2_w  (384 outputs, computed once)
        int i = (blockIdx.x - COUNT_BLOCKS - WSPLIT_BLOCKS) * 256 + threadIdx.x;
        if (i < 3 * D) {
            float s = 0.f;
            #pragma unroll 16
            for (int o = 0; o < D; o++) s += w2[o] * W[o * (3 * D) + i];
            g_u[i] = s;
        }
    }
}

// ============================================================================
// K2: co-launched scan (blocks [0,13)) and node/rel scalar scores (rest).
//   Scores depend only on g_u (K1); scan blocks run concurrently.
// ============================================================================
__global__ void __launch_bounds__(1024) k_scan_scores(const float* __restrict__ h,
                                                      const float* __restrict__ emb_rel) {
    if (blockIdx.x < SCAN_BLOCKS) {
        // ---- decoupled-lookback exclusive scan, 1024 thr x 4 items ----
        __shared__ int sm[1024];
        __shared__ int s_prefix;
        int b = blockIdx.x, t = threadIdx.x;
        int4 v = ((const int4*)g_deg)[b * 1024 + t];
        int tot = v.x + v.y + v.z + v.w;
        sm[t] = tot;
        __syncthreads();
        #pragma unroll
        for (int off = 1; off < 1024; off <<= 1) {
            int val = (t >= off) ? sm[t - off] : 0;
            __syncthreads();
            sm[t] += val;
            __syncthreads();
        }
        if (t == 1023) {
            int inc = sm[1023];
            int p = 0;
            if (b > 0) {
                volatile int* pub = g_scan_pub;
                int x;
                do { x = pub[b - 1]; } while (x == 0);
                p = x - 1;
            }
            ((volatile int*)g_scan_pub)[b] = p + inc + 1;
            s_prefix = p;
        }
        __syncthreads();
        int pre = s_prefix + sm[t] - tot;
        int4 o;
        o.x = pre;
        o.y = pre + v.x;
        o.z = o.y + v.y;
        o.w = o.z + v.z;
        ((int4*)g_off)[b * 1024 + t] = o;
    } else {
        // ---- scores: each warp handles 32 units; u loaded from global ----
        int t = threadIdx.x;
        int lane = t & 31;
        int wid  = t >> 5;
        float4 u0 = ((const float4*)g_u)[lane];        // u_s
        float4 u1 = ((const float4*)g_u)[32 + lane];   // u_t
        float4 u2 = ((const float4*)g_u)[64 + lane];   // u_r
        int base = ((blockIdx.x - SCAN_BLOCKS) * 32 + wid) * 32;
        #pragma unroll 4
        for (int i = 0; i < 32; i++) {
            int gw = base + i;
            if (gw < N_NODES) {
                float4 hv = ((const float4*)h)[gw * 32 + lane];
                float ss = hv.x * u0.x + hv.y * u0.y + hv.z * u0.z + hv.w * u0.w;
                float sd = hv.x * u1.x + hv.y * u1.y + hv.z * u1.z + hv.w * u1.w;
                #pragma unroll
                for (int o = 16; o; o >>= 1) {
                    ss += __shfl_xor_sync(0xffffffffu, ss, o);
                    sd += __shfl_xor_sync(0xffffffffu, sd, o);
                }
                if (lane == 0) { g_s_src[gw] = ss; g_s_dst[gw] = sd; }
            } else if (gw < N_NODES + N_RELS) {
                int r = gw - N_NODES;
                float4 rv = ((const float4*)emb_rel)[r * 32 + lane];
                float sr = rv.x * u2.x + rv.y * u2.y + rv.z * u2.z + rv.w * u2.w;
                #pragma unroll
                for (int o = 16; o; o >>= 1) sr += __shfl_xor_sync(0xffffffffu, sr, o);
                if (lane == 0) g_s_rel[r] = sr;
            }
        }
    }
}

// ============================================================================
// K3: MERGED independent work: HMMA GEMM tile (blocks [0,782)) and
//     edge fill (blocks [782, 782+586)). No dependence between the halves.
// ============================================================================
#define A_STRIDE 272                        // 17*16: 16B-aligned rows
#define SM_A_HI  0
#define SM_A_LO  (64 * A_STRIDE)            // 17408
#define GEMM_SMEM (2 * 64 * A_STRIDE)       // 34816

__global__ void __launch_bounds__(256) k_gemm_fill(const float* __restrict__ h,
                                                   float* __restrict__ out,
                                                   const int* __restrict__ esrc,
                                                   const int* __restrict__ edst,
                                                   const int* __restrict__ etype) {
    extern __shared__ char smc[];
    int tid = threadIdx.x;

    if (blockIdx.x >= GEMM_BLOCKS) {
        // ================= edge fill =================
        int i4 = (blockIdx.x - GEMM_BLOCKS) * 256 + tid;
        if (i4 * 4 >= N_EDGES) return;
        int4 s4 = ((const int4*)esrc)[i4];
        int4 d4 = ((const int4*)edst)[i4];
        int4 t4 = ((const int4*)etype)[i4];
        #pragma unroll
        for (int j = 0; j < 4; j++) {
            int s = (j == 0) ? s4.x : (j == 1) ? s4.y : (j == 2) ? s4.z : s4.w;
            int d = (j == 0) ? d4.x : (j == 1) ? d4.y : (j == 2) ? d4.z : d4.w;
            int r = (j == 0) ? t4.x : (j == 1) ? t4.y : (j == 2) ? t4.z : t4.w;
            float e = g_s_src[s] + g_s_dst[d] + g_s_rel[r];
            e = (e >= 0.f) ? e : 0.01f * e;
            int pos = g_off[d] + (atomicSub(&g_deg[d], 1) - 1);
            g_edge[pos] = make_uint2(__float_as_uint(__expf(e)), (unsigned)s);
        }
        return;
    }

    // ================= GEMM (round-7 validated path) =================
    unsigned sb = smem_u32(smc);
    int lane = tid & 31, wid = tid >> 5;
    int row0 = blockIdx.x * 64;

    #pragma unroll
    for (int i = 0; i < 8; i++) {
        int idx = tid + i * 256;
        int r = idx >> 5, c4 = idx & 31;
        int row = row0 + r;
        float4 v = (row < N_NODES) ? ((const float4*)h)[row * 32 + c4]
                                   : make_float4(0.f, 0.f, 0.f, 0.f);
        __nv_bfloat162 h01 = __floats2bfloat162_rn(v.x, v.y);
        __nv_bfloat162 h23 = __floats2bfloat162_rn(v.z, v.w);
        float lx = v.x - __bfloat162float(__low2bfloat16(h01));
        float ly = v.y - __bfloat162float(__high2bfloat16(h01));
        float lz = v.z - __bfloat162float(__low2bfloat16(h23));
        float lw = v.w - __bfloat162float(__high2bfloat16(h23));
        __nv_bfloat162 l01 = __floats2bfloat162_rn(lx, ly);
        __nv_bfloat162 l23 = __floats2bfloat162_rn(lz, lw);
        unsigned off = r * A_STRIDE + c4 * 8;
        *(uint2*)(smc + SM_A_HI + off) = make_uint2(*(unsigned*)&h01, *(unsigned*)&h23);
        *(uint2*)(smc + SM_A_LO + off) = make_uint2(*(unsigned*)&l01, *(unsigned*)&l23);
    }
    __syncthreads();

    int g = lane >> 2, t = lane & 3;
    int wm = (wid & 1) * 32;
    int wn = (wid >> 1) * 32;

    unsigned aAddr = sb + SM_A_HI + (wm + (lane & 15)) * A_STRIDE + (lane >> 4) * 16;
    const uint4* __restrict__ wf = g_wfrag + (wn >> 3) * 256 + lane;

    float acc[2][4][4];
    #pragma unroll
    for (int a = 0; a < 2; a++)
        #pragma unroll
        for (int b2 = 0; b2 < 4; b2++)
            #pragma unroll
            for (int c = 0; c < 4; c++) acc[a][b2][c] = 0.f;

    #pragma unroll
    for (int ks = 0; ks < 8; ks++) {
        unsigned ahi[2][4], alo[2][4];
        #pragma unroll
        for (int mt = 0; mt < 2; mt++) {
            unsigned addr = aAddr + mt * (16 * A_STRIDE) + ks * 32;
            LDSM4(ahi[mt], addr);
            LDSM4(alo[mt], addr + (unsigned)SM_A_LO);
        }
        #pragma unroll
        for (int nt = 0; nt < 4; nt++) {
            uint4 f = wf[nt * 256 + ks * 32];
            #pragma unroll
            for (int mt = 0; mt < 2; mt++) {
                MMA16816(acc[mt][nt], ahi[mt], f.x, f.y);
                MMA16816(acc[mt][nt], ahi[mt], f.z, f.w);
                MMA16816(acc[mt][nt], alo[mt], f.x, f.y);
            }
        }
    }

    #pragma unroll
    for (int mt = 0; mt < 2; mt++) {
        int r0 = row0 + wm + mt * 16 + g;
        #pragma unroll
        for (int nt = 0; nt < 4; nt++) {
            int col = wn + nt * 8 + 2 * t;
            if (r0 < N_NODES)
                *(float2*)(out + r0 * D + col) = make_float2(acc[mt][nt][0], acc[mt][nt][1]);
            if (r0 + 8 < N_NODES)
                *(float2*)(out + (r0 + 8) * D + col) = make_float2(acc[mt][nt][2], acc[mt][nt][3]);
        }
    }
}

// ============================================================================
// K4: per-dst softmax-weighted gather-sum (validated round-11 form).
// ============================================================================
__global__ void k_aggregate(const float* __restrict__ h, float* __restrict__ out) {
    int lane = threadIdx.x & 31;
    int n = blockIdx.x * 8 + (threadIdx.x >> 5);
    if (n >= N_NODES) return;
    int beg = g_off[n], end = g_off[n + 1];
    if (beg == end) return;

    float4 acc = {0.f, 0.f, 0.f, 0.f};
    float den = 0.f;
    int j = beg;
    for (; j + 4 <= end; j += 4) {
        uint2 e0 = g_edge[j],     e1 = g_edge[j + 1];
        uint2 e2 = g_edge[j + 2], e3 = g_edge[j + 3];
        float4 h0 = ((const float4*)h)[e0.y * 32 + lane];
        float4 h1 = ((const float4*)h)[e1.y * 32 + lane];
        float4 h2 = ((const float4*)h)[e2.y * 32 + lane];
        float4 h3 = ((const float4*)h)[e3.y * 32 + lane];
        float x0 = __uint_as_float(e0.x), x1 = __uint_as_float(e1.x);
        float x2 = __uint_as_float(e2.x), x3 = __uint_as_float(e3.x);
        den += (x0 + x1) + (x2 + x3);
        acc.x += x0 * h0.x + x1 * h1.x + x2 * h2.x + x3 * h3.x;
        acc.y += x0 * h0.y + x1 * h1.y + x2 * h2.y + x3 * h3.y;
        acc.z += x0 * h0.z + x1 * h1.z + x2 * h2.z + x3 * h3.z;
        acc.w += x0 * h0.w + x1 * h1.w + x2 * h2.w + x3 * h3.w;
    }
    for (; j < end; j++) {
        uint2 e0 = g_edge[j];
        float4 h0 = ((const float4*)h)[e0.y * 32 + lane];
        float x0 = __uint_as_float(e0.x);
        den += x0;
        acc.x += x0 * h0.x; acc.y += x0 * h0.y;
        acc.z += x0 * h0.z; acc.w += x0 * h0.w;
    }
    float inv = 1.f / den;
    float4* op = (float4*)out + n * 32 + lane;
    float4 o = *op;
    o.x += acc.x * inv; o.y += acc.y * inv;
    o.z += acc.z * inv; o.w += acc.w * inv;
    *op = o;
}

// ---------------- launch ----------------
extern "C" void kernel_launch(void* const* d_in, const int* in_sizes, int n_in,
                              void* d_out, int out_size) {
    const float* h          = (const float*)d_in[0];
    const float* emb_rel    = (const float*)d_in[1];
    const float* attn_fc_w  = (const float*)d_in[2];
    const float* attn_fc2_w = (const float*)d_in[3];
    const float* loop_w     = (const float*)d_in[4];
    const int*   esrc       = (const int*)d_in[5];
    const int*   edst       = (const int*)d_in[6];
    const int*   etype      = (const int*)d_in[7];
    float* out = (float*)d_out;

    cudaFuncSetAttribute(k_gemm_fill, cudaFuncAttributeMaxDynamicSharedMemorySize, GEMM_SMEM);

    k_prep<<<COUNT_BLOCKS + WSPLIT_BLOCKS + U_BLOCKS, 256>>>(attn_fc_w, attn_fc2_w, edst, loop_w);
    k_scan_scores<<<SCAN_BLOCKS + SCORE_BLOCKS, 1024>>>(h, emb_rel);
    k_gemm_fill<<<GEMM_BLOCKS + COUNT_BLOCKS, 256, GEMM_SMEM>>>(h, out, esrc, edst, etype);
    k_aggregate<<<(N_NODES + 7) / 8, 256>>>(h, out);
}